// round 13
// baseline (speedup 1.0000x reference)
#include <cuda_runtime.h>

#define DEV __device__ __forceinline__

// ---------------- shared-memory weight layout (floats) ----------------
static constexpr int OFF_WSELF = 0;                       // 15*128
static constexpr int OFF_BSELF = OFF_WSELF + 15 * 128;    // 128
static constexpr int OFF_WDYN  = OFF_BSELF + 128;         // 128*64
static constexpr int OFF_BDYN  = OFF_WDYN + 128 * 64;     // 64
static constexpr int OFF_HWH   = OFF_BDYN + 64;           // 3*3*16
static constexpr int OFF_HA1   = OFF_HWH + 144;           // 48
static constexpr int OFF_HA2   = OFF_HA1 + 48;            // 48
static constexpr int OFF_HWO   = OFF_HA2 + 48;            // 48*64
static constexpr int OFF_HWA1  = OFF_HWO + 48 * 64;       // 48  (hWo @ hao1)
static constexpr int OFF_HWA2  = OFF_HWA1 + 48;           // 48  (hWo @ hao2)
static constexpr int OFF_CWH   = OFF_HWA2 + 48;
static constexpr int OFF_CA1   = OFF_CWH + 144;
static constexpr int OFF_CA2   = OFF_CA1 + 48;
static constexpr int OFF_CWO   = OFF_CA2 + 48;
static constexpr int OFF_CWA1  = OFF_CWO + 48 * 64;
static constexpr int OFF_CWA2  = OFF_CWA1 + 48;
static constexpr int OFF_LW1   = OFF_CWA2 + 48;           // 108*64
static constexpr int OFF_LB1   = OFF_LW1 + 108 * 64;      // 64
static constexpr int OFF_LW2   = OFF_LB1 + 64;            // 64*64
static constexpr int OFF_LB2   = OFF_LW2 + 64 * 64;       // 64
static constexpr int OFF_CMW1  = OFF_LB2 + 64;            // 269*64
static constexpr int OFF_CMB1  = OFF_CMW1 + 269 * 64;     // 64
static constexpr int OFF_CMW2  = OFF_CMB1 + 64;           // 64*64
static constexpr int OFF_CMB2  = OFF_CMW2 + 64 * 64;      // 64
static constexpr int SMEM_FLOATS = OFF_CMB2 + 64;         // 49696 floats = 198784 B

static constexpr int OBS_STRIDE = 2064;   // 6 * 344
static constexpr int CUR = 5 * 344;       // 1720

static constexpr int BLOCK = 224;
static constexpr int GRID  = 148;

// obs prefetch buffer layout (per-thread local memory)
static constexpr int OB_HIST = 0;    // 15 (steps 1..5 self[0:3]; [12..14] = current ego)
static constexpr int OB_HDV  = 15;   // 12 nodes x 3
static constexpr int OB_CAV  = 51;   // 8 nodes x 3
static constexpr int OB_LANE = 75;   // 108
static constexpr int OB_ROAD = 183;  // 13 (pre-ordered)
static constexpr int OB_SIZE = 196;

DEV float lrelu2(float z)  { return z > 0.f ? z : 0.01f * z; }  // leaky(leaky(.,0.1),0.1)
DEV float lrelu02(float z) { return z > 0.f ? z : 0.2f  * z; }
DEV float eluf(float z)    { return z > 0.f ? z : (__expf(z) - 1.f); }

DEV void cp4(float* dst, const float* __restrict__ src, int n4, int tid, int bd) {
    float4* d = reinterpret_cast<float4*>(dst);
    const float4* sp = reinterpret_cast<const float4*>(src);
    for (int i = tid; i < n4; i += bd) d[i] = sp[i];
}

// acc[64] += v * row[0..63] (smem, 16B aligned). Fully unrolled (static acc idx).
DEV void gv64(float (&acc)[64], float v, const float* row) {
    const float4* w = reinterpret_cast<const float4*>(row);
    #pragma unroll
    for (int j = 0; j < 16; j++) {
        float4 q = w[j];
        acc[4*j+0] = fmaf(v, q.x, acc[4*j+0]);
        acc[4*j+1] = fmaf(v, q.y, acc[4*j+1]);
        acc[4*j+2] = fmaf(v, q.z, acc[4*j+2]);
        acc[4*j+3] = fmaf(v, q.w, acc[4*j+3]);
    }
}

// Dual-k GEMV step: acc += v0*r0 + v1*r1. Per-acc order (v0 then v1) matches the
// serial k,k+1 order -> bit-identical numerics. Loads batch ahead of FMA drain.
DEV void gv64_2(float (&acc)[64], float v0, float v1, const float* r0, const float* r1) {
    const float4* w0 = reinterpret_cast<const float4*>(r0);
    const float4* w1 = reinterpret_cast<const float4*>(r1);
    #pragma unroll
    for (int j = 0; j < 16; j++) {
        float4 q0 = w0[j];
        float4 q1 = w1[j];
        acc[4*j+0] = fmaf(v0, q0.x, acc[4*j+0]);
        acc[4*j+1] = fmaf(v0, q0.y, acc[4*j+1]);
        acc[4*j+2] = fmaf(v0, q0.z, acc[4*j+2]);
        acc[4*j+3] = fmaf(v0, q0.w, acc[4*j+3]);
        acc[4*j+0] = fmaf(v1, q1.x, acc[4*j+0]);
        acc[4*j+1] = fmaf(v1, q1.y, acc[4*j+1]);
        acc[4*j+2] = fmaf(v1, q1.z, acc[4*j+2]);
        acc[4*j+3] = fmaf(v1, q1.w, acc[4*j+3]);
    }
}

// acc[64] += stage[0..K-1] (local mem) @ sW[K x 64] (smem rows), unroll 2 over k.
DEV void gemv_stage(float (&acc)[64], volatile const float* st, const float* sW, int K) {
    int k = 0;
    #pragma unroll 1
    for (; k + 1 < K; k += 2) {
        float v0 = st[k];
        float v1 = st[k + 1];
        gv64_2(acc, v0, v1, sW + k * 64, sW + k * 64 + 64);
    }
    if (k < K) gv64(acc, st[k], sW + k * 64);
}

DEV void initAcc(float (&acc)[64], const float* bias) {
    const float4* bp = reinterpret_cast<const float4*>(bias);
    #pragma unroll
    for (int j = 0; j < 16; j++) {
        float4 q = bp[j];
        acc[4*j+0] = q.x; acc[4*j+1] = q.y; acc[4*j+2] = q.z; acc[4*j+3] = q.w;
    }
}

// Star-GAT collapsed: writes blended 48-vector (wE*x2_ego + wOtot*x2_other) to xbout.
// Node coords come from the prefetched local buffer (nd[3m..3m+2]).
template<int N>
DEV void gat_blend(volatile const float* nd,            // nodes 1..N-1, 3 floats each
                   float e0, float e1, float e2,        // ego node coords
                   const float* s, int WH, int A1, int A2, int WA1, int WA2,
                   volatile float* xbout)
{
    float x2e[48], x2o[48];
    #pragma unroll
    for (int h = 0; h < 3; h++) {
        const float* Wh = s + WH + h * 48;   // [3][16]
        const float* a1 = s + A1 + h * 16;
        const float* a2 = s + A2 + h * 16;
        float h0[16];
        float s1 = 0.f, s20 = 0.f;
        #pragma unroll
        for (int t = 0; t < 16; t++) {
            float hv = fmaf(e0, Wh[t], fmaf(e1, Wh[16 + t], e2 * Wh[32 + t]));
            h0[t] = hv;
            s1  = fmaf(a1[t], hv, s1);
            s20 = fmaf(a2[t], hv, s20);
        }
        float w0 = __expf(lrelu02(s1 + s20));
        float den = w0;
        float ws[16];
        #pragma unroll
        for (int t = 0; t < 16; t++) ws[t] = w0 * h0[t];
        #pragma unroll 1
        for (int m = 0; m < N - 1; m++) {
            float x0 = nd[3 * m + 0], x1 = nd[3 * m + 1], x2v = nd[3 * m + 2];
            float hm[16]; float s2 = 0.f;
            #pragma unroll
            for (int t = 0; t < 16; t++) {
                float hv = fmaf(x0, Wh[t], fmaf(x1, Wh[16 + t], x2v * Wh[32 + t]));
                hm[t] = hv;
                s2 = fmaf(a2[t], hv, s2);
            }
            float wm = __expf(lrelu02(s1 + s2));
            den += wm;
            #pragma unroll
            for (int t = 0; t < 16; t++) ws[t] = fmaf(wm, hm[t], ws[t]);
        }
        float inv = __fdividef(1.f, den);
        #pragma unroll
        for (int t = 0; t < 16; t++) {
            x2e[h * 16 + t] = eluf(ws[t] * inv);   // ego layer-1 output (concat heads)
            x2o[h * 16 + t] = eluf(h0[t]);         // identical layer-1 output of non-ego nodes
        }
    }
    float d1e = 0.f, d2e = 0.f, d2o = 0.f;
    #pragma unroll
    for (int k = 0; k < 48; k++) {
        d1e = fmaf(x2e[k], s[WA1 + k], d1e);
        d2e = fmaf(x2e[k], s[WA2 + k], d2e);
        d2o = fmaf(x2o[k], s[WA2 + k], d2o);
    }
    float we = __expf(lrelu02(d1e + d2e));
    float wo = (float)(N - 1) * __expf(lrelu02(d1e + d2o));
    float inv = __fdividef(1.f, we + wo);
    we *= inv; wo *= inv;
    #pragma unroll
    for (int k = 0; k < 48; k++) xbout[k] = fmaf(we, x2e[k], wo * x2o[k]);
}

__global__ void __launch_bounds__(BLOCK, 1) pred_kernel(
    const float* __restrict__ obs,
    const float* __restrict__ W_self, const float* __restrict__ b_self,
    const float* __restrict__ W_dyn,  const float* __restrict__ b_dyn,
    const float* __restrict__ hWh, const float* __restrict__ ha1, const float* __restrict__ ha2,
    const float* __restrict__ hWo, const float* __restrict__ hao1, const float* __restrict__ hao2,
    const float* __restrict__ cWh, const float* __restrict__ ca1v, const float* __restrict__ ca2v,
    const float* __restrict__ cWo, const float* __restrict__ cao1, const float* __restrict__ cao2,
    const float* __restrict__ lW1, const float* __restrict__ lb1,
    const float* __restrict__ lW2, const float* __restrict__ lb2,
    const float* __restrict__ cmW1, const float* __restrict__ cmb1,
    const float* __restrict__ cmW2, const float* __restrict__ cmb2,
    float* __restrict__ out, int B)
{
    extern __shared__ float s[];
    const int tid = threadIdx.x, bd = blockDim.x;

    cp4(s + OFF_WSELF, W_self, 15 * 128 / 4, tid, bd);
    cp4(s + OFF_BSELF, b_self, 128 / 4, tid, bd);
    cp4(s + OFF_WDYN,  W_dyn,  128 * 64 / 4, tid, bd);
    cp4(s + OFF_BDYN,  b_dyn,  64 / 4, tid, bd);
    cp4(s + OFF_HWH,   hWh,    144 / 4, tid, bd);
    cp4(s + OFF_HA1,   ha1,    48 / 4, tid, bd);
    cp4(s + OFF_HA2,   ha2,    48 / 4, tid, bd);
    cp4(s + OFF_HWO,   hWo,    48 * 64 / 4, tid, bd);
    cp4(s + OFF_CWH,   cWh,    144 / 4, tid, bd);
    cp4(s + OFF_CA1,   ca1v,   48 / 4, tid, bd);
    cp4(s + OFF_CA2,   ca2v,   48 / 4, tid, bd);
    cp4(s + OFF_CWO,   cWo,    48 * 64 / 4, tid, bd);
    cp4(s + OFF_LW1,   lW1,    108 * 64 / 4, tid, bd);
    cp4(s + OFF_LB1,   lb1,    64 / 4, tid, bd);
    cp4(s + OFF_LW2,   lW2,    64 * 64 / 4, tid, bd);
    cp4(s + OFF_LB2,   lb2,    64 / 4, tid, bd);
    cp4(s + OFF_CMW1,  cmW1,   269 * 64 / 4, tid, bd);
    cp4(s + OFF_CMB1,  cmb1,   64 / 4, tid, bd);
    cp4(s + OFF_CMW2,  cmW2,   64 * 64 / 4, tid, bd);
    cp4(s + OFF_CMB2,  cmb2,   64 / 4, tid, bd);

    // Precompute Wo@ao1 / Wo@ao2 for both GATs (48 values each)
    if (tid < 192) {
        int g = tid / 48;
        int r = tid - g * 48;
        const float* Wo = (g < 2) ? hWo : cWo;
        const float* ao = (g == 0) ? hao1 : (g == 1) ? hao2 : (g == 2) ? cao1 : cao2;
        int dst = (g == 0) ? OFF_HWA1 : (g == 1) ? OFF_HWA2 : (g == 2) ? OFF_CWA1 : OFF_CWA2;
        float sum = 0.f;
        #pragma unroll 1
        for (int j = 0; j < 64; j++) sum = fmaf(Wo[r * 64 + j], ao[j], sum);
        s[dst + r] = sum;
    }
    __syncthreads();

    const int b = blockIdx.x * BLOCK + tid;
    if (b >= B) return;
    const float* o = obs + (long long)b * OBS_STRIDE;

    // ---- batched obs prefetch: issue ALL global loads up front (high MLP), ----
    // ---- then every compute loop reads cheap coalesced local-memory words.  ----
    volatile float ob[OB_SIZE];
    #pragma unroll
    for (int st5 = 0; st5 < 5; st5++) {
        const float* p = o + (st5 + 1) * 344 + 234;
        ob[OB_HIST + st5 * 3 + 0] = p[0];
        ob[OB_HIST + st5 * 3 + 1] = p[1];
        ob[OB_HIST + st5 * 3 + 2] = p[2];
    }
    #pragma unroll
    for (int m = 0; m < 12; m++) {
        const float* p = o + CUR + m * 6;
        ob[OB_HDV + m * 3 + 0] = p[0];
        ob[OB_HDV + m * 3 + 1] = p[1];
        ob[OB_HDV + m * 3 + 2] = p[2];
    }
    #pragma unroll
    for (int m = 0; m < 8; m++) {
        const float* p = o + CUR + 72 + m * 6;
        ob[OB_CAV + m * 3 + 0] = p[0];
        ob[OB_CAV + m * 3 + 1] = p[1];
        ob[OB_CAV + m * 3 + 2] = p[2];
    }
    {
        const float4* lp = reinterpret_cast<const float4*>(o + CUR + 120);
        #pragma unroll
        for (int i = 0; i < 27; i++) {
            float4 v = lp[i];
            ob[OB_LANE + 4 * i + 0] = v.x;
            ob[OB_LANE + 4 * i + 1] = v.y;
            ob[OB_LANE + 4 * i + 2] = v.z;
            ob[OB_LANE + 4 * i + 3] = v.w;
        }
    }
    ob[OB_ROAD + 0]  = o[CUR + 228]; ob[OB_ROAD + 1]  = o[CUR + 229];   // bott
    ob[OB_ROAD + 2]  = o[CUR + 247]; ob[OB_ROAD + 3]  = o[CUR + 248];   // dist_bott
    ob[OB_ROAD + 4]  = o[CUR + 230]; ob[OB_ROAD + 5]  = o[CUR + 231];   // road_end
    ob[OB_ROAD + 6]  = o[CUR + 249]; ob[OB_ROAD + 7]  = o[CUR + 250];   // dist_end
    ob[OB_ROAD + 8]  = o[CUR + 232]; ob[OB_ROAD + 9]  = o[CUR + 233];   // target
    ob[OB_ROAD + 10] = o[CUR + 253];                                     // gen
    ob[OB_ROAD + 11] = o[CUR + 251]; ob[OB_ROAD + 12] = o[CUR + 252];    // exe

    volatile float stage[64];   // GEMV multiplier staging (local mem)
    float ca[64];               // comb-MLP hidden accumulator (persists)
    float acc[64];              // working accumulator (reused)

    initAcc(ca, s + OFF_CMB1);

    const float e0g = ob[OB_HIST + 12], e1g = ob[OB_HIST + 13], e2g = ob[OB_HIST + 14];

    // ----- HDV GAT (comb rows 64..127) -----
    gat_blend<13>(ob + OB_HDV, e0g, e1g, e2g, s, OFF_HWH, OFF_HA1, OFF_HA2,
                  OFF_HWA1, OFF_HWA2, stage);
    #pragma unroll
    for (int j = 0; j < 64; j++) acc[j] = 0.f;
    gemv_stage(acc, stage, s + OFF_HWO, 48);
    #pragma unroll
    for (int j = 0; j < 64; j++) stage[j] = eluf(acc[j]);
    gemv_stage(ca, stage, s + OFF_CMW1 + 64 * 64, 64);

    // ----- CAV GAT (comb rows 128..191) -----
    gat_blend<9>(ob + OB_CAV, e0g, e1g, e2g, s, OFF_CWH, OFF_CA1, OFF_CA2,
                 OFF_CWA1, OFF_CWA2, stage);
    #pragma unroll
    for (int j = 0; j < 64; j++) acc[j] = 0.f;
    gemv_stage(acc, stage, s + OFF_CWO, 48);
    #pragma unroll
    for (int j = 0; j < 64; j++) stage[j] = eluf(acc[j]);
    gemv_stage(ca, stage, s + OFF_CMW1 + 128 * 64, 64);

    // ----- ego feature (comb rows 0..63): leaky2(ehist@W_self+b_self)@W_dyn+b_dyn -----
    initAcc(acc, s + OFF_BDYN);
    {
        float eh[15];
        #pragma unroll
        for (int i = 0; i < 15; i++) eh[i] = ob[OB_HIST + i];
        #pragma unroll 1
        for (int kg = 0; kg < 32; kg++) {   // 4 hidden columns at a time (float4 rows)
            float4 zb = reinterpret_cast<const float4*>(s + OFF_BSELF)[kg];
            float z0 = zb.x, z1 = zb.y, z2 = zb.z, z3 = zb.w;
            #pragma unroll
            for (int i = 0; i < 15; i++) {
                float4 w = reinterpret_cast<const float4*>(s + OFF_WSELF + i * 128)[kg];
                z0 = fmaf(eh[i], w.x, z0);
                z1 = fmaf(eh[i], w.y, z1);
                z2 = fmaf(eh[i], w.z, z2);
                z3 = fmaf(eh[i], w.w, z3);
            }
            gv64_2(acc, lrelu2(z0), lrelu2(z1),
                   s + OFF_WDYN + (4 * kg + 0) * 64, s + OFF_WDYN + (4 * kg + 1) * 64);
            gv64_2(acc, lrelu2(z2), lrelu2(z3),
                   s + OFF_WDYN + (4 * kg + 2) * 64, s + OFF_WDYN + (4 * kg + 3) * 64);
        }
    }
    #pragma unroll
    for (int j = 0; j < 64; j++) stage[j] = acc[j];
    gemv_stage(ca, stage, s + OFF_CMW1 + 0 * 64, 64);

    // ----- lane MLP (comb rows 192..255) -----
    initAcc(acc, s + OFF_LB1);
    #pragma unroll 1
    for (int k4 = 0; k4 < 27; k4++) {
        float vx = ob[OB_LANE + 4 * k4 + 0];
        float vy = ob[OB_LANE + 4 * k4 + 1];
        float vz = ob[OB_LANE + 4 * k4 + 2];
        float vw = ob[OB_LANE + 4 * k4 + 3];
        gv64_2(acc, vx, vy, s + OFF_LW1 + (4 * k4 + 0) * 64, s + OFF_LW1 + (4 * k4 + 1) * 64);
        gv64_2(acc, vz, vw, s + OFF_LW1 + (4 * k4 + 2) * 64, s + OFF_LW1 + (4 * k4 + 3) * 64);
    }
    #pragma unroll
    for (int j = 0; j < 64; j++) stage[j] = fmaxf(acc[j], 0.f);
    initAcc(acc, s + OFF_LB2);
    gemv_stage(acc, stage, s + OFF_LW2, 64);
    #pragma unroll
    for (int j = 0; j < 64; j++) stage[j] = fmaxf(acc[j], 0.f);
    gemv_stage(ca, stage, s + OFF_CMW1 + 192 * 64, 64);

    // ----- road / gen / exe (comb rows 256..268) -----
    gemv_stage(ca, ob + OB_ROAD, s + OFF_CMW1 + 256 * 64, 13);

    // ----- final layer: relu(relu(ca) @ cmW2 + cmb2) -----
    #pragma unroll
    for (int j = 0; j < 64; j++) stage[j] = fmaxf(ca[j], 0.f);
    initAcc(acc, s + OFF_CMB2);
    gemv_stage(acc, stage, s + OFF_CMW2, 64);

    float4* op = reinterpret_cast<float4*>(out + (long long)b * 64);
    #pragma unroll
    for (int j = 0; j < 16; j++) {
        float4 q;
        q.x = fmaxf(acc[4*j+0], 0.f);
        q.y = fmaxf(acc[4*j+1], 0.f);
        q.z = fmaxf(acc[4*j+2], 0.f);
        q.w = fmaxf(acc[4*j+3], 0.f);
        op[j] = q;
    }
}

extern "C" void kernel_launch(void* const* d_in, const int* in_sizes, int n_in,
                              void* d_out, int out_size) {
    const float* obs    = (const float*)d_in[0];
    const float* W_self = (const float*)d_in[1];
    const float* b_self = (const float*)d_in[2];
    const float* W_dyn  = (const float*)d_in[3];
    const float* b_dyn  = (const float*)d_in[4];
    const float* hWh    = (const float*)d_in[5];
    const float* ha1    = (const float*)d_in[6];
    const float* ha2    = (const float*)d_in[7];
    const float* hWo    = (const float*)d_in[8];
    const float* hao1   = (const float*)d_in[9];
    const float* hao2   = (const float*)d_in[10];
    const float* cWh    = (const float*)d_in[11];
    const float* ca1v   = (const float*)d_in[12];
    const float* ca2v   = (const float*)d_in[13];
    const float* cWo    = (const float*)d_in[14];
    const float* cao1   = (const float*)d_in[15];
    const float* cao2   = (const float*)d_in[16];
    const float* lW1    = (const float*)d_in[17];
    const float* lb1    = (const float*)d_in[18];
    const float* lW2    = (const float*)d_in[19];
    const float* lb2    = (const float*)d_in[20];
    const float* cmW1   = (const float*)d_in[21];
    const float* cmb1   = (const float*)d_in[22];
    const float* cmW2   = (const float*)d_in[23];
    const float* cmb2   = (const float*)d_in[24];

    int B = in_sizes[0] / OBS_STRIDE;
    size_t smem = (size_t)SMEM_FLOATS * sizeof(float);
    cudaFuncSetAttribute(pred_kernel, cudaFuncAttributeMaxDynamicSharedMemorySize, (int)smem);

    dim3 block(BLOCK);
    dim3 grid(GRID);
    pred_kernel<<<grid, block, smem>>>(
        obs, W_self, b_self, W_dyn, b_dyn,
        hWh, ha1, ha2, hWo, hao1, hao2,
        cWh, ca1v, ca2v, cWo, cao1, cao2,
        lW1, lb1, lW2, lb2,
        cmW1, cmb1, cmW2, cmb2,
        (float*)d_out, B);
}

// round 14
// speedup vs baseline: 1.1675x; 1.1675x over previous
#include <cuda_runtime.h>

#define DEV __device__ __forceinline__

// ---------------- shared-memory weight layout (floats) ----------------
static constexpr int OFF_WSELF = 0;                       // 15*128
static constexpr int OFF_BSELF = OFF_WSELF + 15 * 128;    // 128
static constexpr int OFF_WDYN  = OFF_BSELF + 128;         // 128*64  (becomes WFUSE = W_dyn @ CMW1_ego)
static constexpr int OFF_BDYN  = OFF_WDYN + 128 * 64;     // 64
static constexpr int OFF_HWH   = OFF_BDYN + 64;           // 3*3*16
static constexpr int OFF_HA1   = OFF_HWH + 144;           // 48
static constexpr int OFF_HA2   = OFF_HA1 + 48;            // 48
static constexpr int OFF_HWO   = OFF_HA2 + 48;            // 48*64
static constexpr int OFF_HWA1  = OFF_HWO + 48 * 64;       // 48  (hWo @ hao1)
static constexpr int OFF_HWA2  = OFF_HWA1 + 48;           // 48  (hWo @ hao2)
static constexpr int OFF_CWH   = OFF_HWA2 + 48;
static constexpr int OFF_CA1   = OFF_CWH + 144;
static constexpr int OFF_CA2   = OFF_CA1 + 48;
static constexpr int OFF_CWO   = OFF_CA2 + 48;
static constexpr int OFF_CWA1  = OFF_CWO + 48 * 64;
static constexpr int OFF_CWA2  = OFF_CWA1 + 48;
static constexpr int OFF_LW1   = OFF_CWA2 + 48;           // 108*64
static constexpr int OFF_LB1   = OFF_LW1 + 108 * 64;      // 64
static constexpr int OFF_LW2   = OFF_LB1 + 64;            // 64*64
static constexpr int OFF_LB2   = OFF_LW2 + 64 * 64;       // 64
static constexpr int OFF_CMW1  = OFF_LB2 + 64;            // 269*64 (rows 0..63 = ego block, used only in precompute)
static constexpr int OFF_CMB1  = OFF_CMW1 + 269 * 64;     // 64 (becomes fused bias CMB1F)
static constexpr int OFF_CMW2  = OFF_CMB1 + 64;           // 64*64
static constexpr int OFF_CMB2  = OFF_CMW2 + 64 * 64;      // 64
static constexpr int SMEM_FLOATS = OFF_CMB2 + 64;         // 49696 floats = 198784 B

static constexpr int OBS_STRIDE = 2064;   // 6 * 344
static constexpr int CUR = 5 * 344;       // 1720

static constexpr int BLOCK = 224;
static constexpr int GRID  = 148;

DEV float lrelu2(float z)  { return z > 0.f ? z : 0.01f * z; }  // leaky(leaky(.,0.1),0.1)
DEV float lrelu02(float z) { return z > 0.f ? z : 0.2f  * z; }
DEV float eluf(float z)    { return z > 0.f ? z : (__expf(z) - 1.f); }

DEV void cp4(float* dst, const float* __restrict__ src, int n4, int tid, int bd) {
    float4* d = reinterpret_cast<float4*>(dst);
    const float4* sp = reinterpret_cast<const float4*>(src);
    for (int i = tid; i < n4; i += bd) d[i] = sp[i];
}

// acc[64] += v * row[0..63] (smem, 16B aligned). Fully unrolled (static acc idx).
DEV void gv64(float (&acc)[64], float v, const float* row) {
    const float4* w = reinterpret_cast<const float4*>(row);
    #pragma unroll
    for (int j = 0; j < 16; j++) {
        float4 q = w[j];
        acc[4*j+0] = fmaf(v, q.x, acc[4*j+0]);
        acc[4*j+1] = fmaf(v, q.y, acc[4*j+1]);
        acc[4*j+2] = fmaf(v, q.z, acc[4*j+2]);
        acc[4*j+3] = fmaf(v, q.w, acc[4*j+3]);
    }
}

// Dual-k GEMV step: acc += v0*r0 + v1*r1. Per-acc order (v0 then v1) matches the
// serial k,k+1 order -> identical numerics. Loads batch ahead of the FMA drain.
DEV void gv64_2(float (&acc)[64], float v0, float v1, const float* r0, const float* r1) {
    const float4* w0 = reinterpret_cast<const float4*>(r0);
    const float4* w1 = reinterpret_cast<const float4*>(r1);
    #pragma unroll
    for (int j = 0; j < 16; j++) {
        float4 q0 = w0[j];
        float4 q1 = w1[j];
        acc[4*j+0] = fmaf(v0, q0.x, acc[4*j+0]);
        acc[4*j+1] = fmaf(v0, q0.y, acc[4*j+1]);
        acc[4*j+2] = fmaf(v0, q0.z, acc[4*j+2]);
        acc[4*j+3] = fmaf(v0, q0.w, acc[4*j+3]);
        acc[4*j+0] = fmaf(v1, q1.x, acc[4*j+0]);
        acc[4*j+1] = fmaf(v1, q1.y, acc[4*j+1]);
        acc[4*j+2] = fmaf(v1, q1.z, acc[4*j+2]);
        acc[4*j+3] = fmaf(v1, q1.w, acc[4*j+3]);
    }
}

// acc[64] += stage[0..K-1] (local mem) @ sW[K x 64] (smem rows), unroll 2 over k.
DEV void gemv_stage(float (&acc)[64], volatile const float* st, const float* sW, int K) {
    int k = 0;
    #pragma unroll 1
    for (; k + 1 < K; k += 2) {
        float v0 = st[k];
        float v1 = st[k + 1];
        gv64_2(acc, v0, v1, sW + k * 64, sW + k * 64 + 64);
    }
    if (k < K) gv64(acc, st[k], sW + k * 64);
}

DEV void initAcc(float (&acc)[64], const float* bias) {
    const float4* bp = reinterpret_cast<const float4*>(bias);
    #pragma unroll
    for (int j = 0; j < 16; j++) {
        float4 q = bp[j];
        acc[4*j+0] = q.x; acc[4*j+1] = q.y; acc[4*j+2] = q.z; acc[4*j+3] = q.w;
    }
}

// Star-GAT collapsed (R5 streamed version: x2e/x2o go to LOCAL arrays to keep
// register peak low; layer-2 attention dots accumulated on the fly).
template<int N>
DEV void gat_collapse(const float* __restrict__ xin,     // nodes 1..N-1, stride 6, first 3 floats
                      float e0, float e1, float e2,      // ego node coords
                      const float* s, int WH, int A1, int A2, int WA1, int WA2,
                      volatile float* lx2e, volatile float* lx2o,
                      float& we_out, float& wo_out)
{
    float d1e = 0.f, d2e = 0.f, d2o = 0.f;
    #pragma unroll 1
    for (int h = 0; h < 3; h++) {
        const float* Wh = s + WH + h * 48;   // [3][16]
        const float* a1 = s + A1 + h * 16;
        const float* a2 = s + A2 + h * 16;
        float h0[16];
        float s1 = 0.f, s20 = 0.f;
        #pragma unroll
        for (int u = 0; u < 16; u++) {
            float hv = fmaf(e0, Wh[u], fmaf(e1, Wh[16 + u], e2 * Wh[32 + u]));
            h0[u] = hv;
            s1  = fmaf(a1[u], hv, s1);
            s20 = fmaf(a2[u], hv, s20);
        }
        float w0 = __expf(lrelu02(s1 + s20));
        float den = w0;
        float ws[16];
        #pragma unroll
        for (int u = 0; u < 16; u++) ws[u] = w0 * h0[u];
        #pragma unroll 1
        for (int m = 0; m < N - 1; m++) {
            const float* xp = xin + m * 6;
            float x0 = xp[0], x1 = xp[1], x2v = xp[2];
            float hm[16]; float s2 = 0.f;
            #pragma unroll
            for (int u = 0; u < 16; u++) {
                float hv = fmaf(x0, Wh[u], fmaf(x1, Wh[16 + u], x2v * Wh[32 + u]));
                hm[u] = hv;
                s2 = fmaf(a2[u], hv, s2);
            }
            float wm = __expf(lrelu02(s1 + s2));
            den += wm;
            #pragma unroll
            for (int u = 0; u < 16; u++) ws[u] = fmaf(wm, hm[u], ws[u]);
        }
        float inv = __fdividef(1.f, den);
        #pragma unroll
        for (int u = 0; u < 16; u++) {
            float xe = eluf(ws[u] * inv);     // ego layer-1 output (concat heads)
            float xo = eluf(h0[u]);           // identical layer-1 output of every non-ego node
            d1e = fmaf(xe, s[WA1 + h * 16 + u], d1e);
            d2e = fmaf(xe, s[WA2 + h * 16 + u], d2e);
            d2o = fmaf(xo, s[WA2 + h * 16 + u], d2o);
            lx2e[h * 16 + u] = xe;
            lx2o[h * 16 + u] = xo;
        }
    }
    float we = __expf(lrelu02(d1e + d2e));
    float wo = (float)(N - 1) * __expf(lrelu02(d1e + d2o));
    float inv = __fdividef(1.f, we + wo);
    we_out = we * inv;
    wo_out = wo * inv;
}

__global__ void __launch_bounds__(BLOCK, 1) pred_kernel(
    const float* __restrict__ obs,
    const float* __restrict__ W_self, const float* __restrict__ b_self,
    const float* __restrict__ W_dyn,  const float* __restrict__ b_dyn,
    const float* __restrict__ hWh, const float* __restrict__ ha1, const float* __restrict__ ha2,
    const float* __restrict__ hWo, const float* __restrict__ hao1, const float* __restrict__ hao2,
    const float* __restrict__ cWh, const float* __restrict__ ca1v, const float* __restrict__ ca2v,
    const float* __restrict__ cWo, const float* __restrict__ cao1, const float* __restrict__ cao2,
    const float* __restrict__ lW1, const float* __restrict__ lb1,
    const float* __restrict__ lW2, const float* __restrict__ lb2,
    const float* __restrict__ cmW1, const float* __restrict__ cmb1,
    const float* __restrict__ cmW2, const float* __restrict__ cmb2,
    float* __restrict__ out, int B)
{
    extern __shared__ float s[];
    const int tid = threadIdx.x, bd = blockDim.x;

    cp4(s + OFF_WSELF, W_self, 15 * 128 / 4, tid, bd);
    cp4(s + OFF_BSELF, b_self, 128 / 4, tid, bd);
    cp4(s + OFF_WDYN,  W_dyn,  128 * 64 / 4, tid, bd);   // temporarily raw W_dyn
    cp4(s + OFF_BDYN,  b_dyn,  64 / 4, tid, bd);
    cp4(s + OFF_HWH,   hWh,    144 / 4, tid, bd);
    cp4(s + OFF_HA1,   ha1,    48 / 4, tid, bd);
    cp4(s + OFF_HA2,   ha2,    48 / 4, tid, bd);
    cp4(s + OFF_HWO,   hWo,    48 * 64 / 4, tid, bd);
    cp4(s + OFF_CWH,   cWh,    144 / 4, tid, bd);
    cp4(s + OFF_CA1,   ca1v,   48 / 4, tid, bd);
    cp4(s + OFF_CA2,   ca2v,   48 / 4, tid, bd);
    cp4(s + OFF_CWO,   cWo,    48 * 64 / 4, tid, bd);
    cp4(s + OFF_LW1,   lW1,    108 * 64 / 4, tid, bd);
    cp4(s + OFF_LB1,   lb1,    64 / 4, tid, bd);
    cp4(s + OFF_LW2,   lW2,    64 * 64 / 4, tid, bd);
    cp4(s + OFF_LB2,   lb2,    64 / 4, tid, bd);
    cp4(s + OFF_CMW1,  cmW1,   269 * 64 / 4, tid, bd);
    cp4(s + OFF_CMB1,  cmb1,   64 / 4, tid, bd);
    cp4(s + OFF_CMW2,  cmW2,   64 * 64 / 4, tid, bd);
    cp4(s + OFF_CMB2,  cmb2,   64 / 4, tid, bd);

    // Precompute Wo@ao1 / Wo@ao2 for both GATs (48 values each)
    if (tid < 192) {
        int g = tid / 48;
        int r = tid - g * 48;
        const float* Wo = (g < 2) ? hWo : cWo;
        const float* ao = (g == 0) ? hao1 : (g == 1) ? hao2 : (g == 2) ? cao1 : cao2;
        int dst = (g == 0) ? OFF_HWA1 : (g == 1) ? OFF_HWA2 : (g == 2) ? OFF_CWA1 : OFF_CWA2;
        float sum = 0.f;
        #pragma unroll 1
        for (int j = 0; j < 64; j++) sum = fmaf(Wo[r * 64 + j], ao[j], sum);
        s[dst + r] = sum;
    }
    __syncthreads();

    // ---- fuse ego path: WFUSE = W_dyn @ CMW1_ego  (ego_feat has no nonlinearity
    // ---- before comb, so the two GEMVs compose). Also fuse b_dyn into the bias.
    {
        volatile float tmp[37];                 // 8192/224 = 36.57 -> <=37 entries/thread
        int n = 0;
        #pragma unroll 1
        for (int idx = tid; idx < 128 * 64; idx += bd, n++) {
            int k = idx >> 6, j = idx & 63;
            float sum = 0.f;
            #pragma unroll 1
            for (int m = 0; m < 64; m++)
                sum = fmaf(s[OFF_WDYN + k * 64 + m], s[OFF_CMW1 + m * 64 + j], sum);
            tmp[n] = sum;
        }
        float bf = 0.f;
        if (tid < 64) {
            bf = s[OFF_CMB1 + tid];
            #pragma unroll 1
            for (int k = 0; k < 64; k++)
                bf = fmaf(s[OFF_BDYN + k], s[OFF_CMW1 + k * 64 + tid], bf);
        }
        __syncthreads();
        n = 0;
        #pragma unroll 1
        for (int idx = tid; idx < 128 * 64; idx += bd, n++) s[OFF_WDYN + idx] = tmp[n];
        if (tid < 64) s[OFF_CMB1 + tid] = bf;   // CMB1F
    }
    __syncthreads();

    const int b = blockIdx.x * BLOCK + tid;
    if (b >= B) return;
    const float* o = obs + (long long)b * OBS_STRIDE;

    volatile float stage[64];   // GEMV multiplier staging (local mem)
    volatile float lx2e[48];
    volatile float lx2o[48];
    float ca[64];               // comb-MLP hidden accumulator (persists)
    float acc[64];              // working accumulator (reused)

    initAcc(ca, s + OFF_CMB1);  // fused bias (cmb1 + b_dyn @ CMW1_ego)

    const float e0g = o[CUR + 234], e1g = o[CUR + 235], e2g = o[CUR + 236];

    // ----- HDV GAT (comb rows 64..127) -----
    {
        float we, wo;
        gat_collapse<13>(o + CUR + 0, e0g, e1g, e2g, s, OFF_HWH, OFF_HA1, OFF_HA2,
                         OFF_HWA1, OFF_HWA2, lx2e, lx2o, we, wo);
        #pragma unroll
        for (int j = 0; j < 64; j++) acc[j] = 0.f;
        #pragma unroll 1
        for (int k = 0; k < 48; k += 2) {
            float v0 = fmaf(we, lx2e[k], wo * lx2o[k]);
            float v1 = fmaf(we, lx2e[k + 1], wo * lx2o[k + 1]);
            gv64_2(acc, v0, v1, s + OFF_HWO + k * 64, s + OFF_HWO + k * 64 + 64);
        }
    }
    #pragma unroll
    for (int j = 0; j < 64; j++) stage[j] = eluf(acc[j]);
    gemv_stage(ca, stage, s + OFF_CMW1 + 64 * 64, 64);

    // ----- CAV GAT (comb rows 128..191) -----
    {
        float we, wo;
        gat_collapse<9>(o + CUR + 72, e0g, e1g, e2g, s, OFF_CWH, OFF_CA1, OFF_CA2,
                        OFF_CWA1, OFF_CWA2, lx2e, lx2o, we, wo);
        #pragma unroll
        for (int j = 0; j < 64; j++) acc[j] = 0.f;
        #pragma unroll 1
        for (int k = 0; k < 48; k += 2) {
            float v0 = fmaf(we, lx2e[k], wo * lx2o[k]);
            float v1 = fmaf(we, lx2e[k + 1], wo * lx2o[k + 1]);
            gv64_2(acc, v0, v1, s + OFF_CWO + k * 64, s + OFF_CWO + k * 64 + 64);
        }
    }
    #pragma unroll
    for (int j = 0; j < 64; j++) stage[j] = eluf(acc[j]);
    gemv_stage(ca, stage, s + OFF_CMW1 + 128 * 64, 64);

    // ----- ego feature fused into comb rows 0..63: ca += lrelu2(eh@WSELF+b)@WFUSE -----
    {
        float eh[15];
        #pragma unroll
        for (int st5 = 0; st5 < 5; st5++) {
            const float* p = o + (st5 + 1) * 344 + 234;
            eh[st5 * 3 + 0] = p[0];
            eh[st5 * 3 + 1] = p[1];
            eh[st5 * 3 + 2] = p[2];
        }
        #pragma unroll 1
        for (int kg = 0; kg < 32; kg++) {   // 4 hidden columns at a time (float4 rows)
            float4 zb = reinterpret_cast<const float4*>(s + OFF_BSELF)[kg];
            float z0 = zb.x, z1 = zb.y, z2 = zb.z, z3 = zb.w;
            #pragma unroll
            for (int i = 0; i < 15; i++) {
                float4 w = reinterpret_cast<const float4*>(s + OFF_WSELF + i * 128)[kg];
                z0 = fmaf(eh[i], w.x, z0);
                z1 = fmaf(eh[i], w.y, z1);
                z2 = fmaf(eh[i], w.z, z2);
                z3 = fmaf(eh[i], w.w, z3);
            }
            gv64_2(ca, lrelu2(z0), lrelu2(z1),
                   s + OFF_WDYN + (4 * kg + 0) * 64, s + OFF_WDYN + (4 * kg + 1) * 64);
            gv64_2(ca, lrelu2(z2), lrelu2(z3),
                   s + OFF_WDYN + (4 * kg + 2) * 64, s + OFF_WDYN + (4 * kg + 3) * 64);
        }
    }

    // ----- lane MLP (comb rows 192..255) -----
    initAcc(acc, s + OFF_LB1);
    {
        const float4* lp = reinterpret_cast<const float4*>(o + CUR + 120);
        #pragma unroll 1
        for (int k4 = 0; k4 < 27; k4++) {
            float4 v = lp[k4];
            gv64_2(acc, v.x, v.y, s + OFF_LW1 + (4 * k4 + 0) * 64, s + OFF_LW1 + (4 * k4 + 1) * 64);
            gv64_2(acc, v.z, v.w, s + OFF_LW1 + (4 * k4 + 2) * 64, s + OFF_LW1 + (4 * k4 + 3) * 64);
        }
    }
    #pragma unroll
    for (int j = 0; j < 64; j++) stage[j] = fmaxf(acc[j], 0.f);
    initAcc(acc, s + OFF_LB2);
    gemv_stage(acc, stage, s + OFF_LW2, 64);
    #pragma unroll
    for (int j = 0; j < 64; j++) stage[j] = fmaxf(acc[j], 0.f);
    gemv_stage(ca, stage, s + OFF_CMW1 + 192 * 64, 64);

    // ----- road / gen / exe (comb rows 256..268) -----
    {
        stage[0]  = o[CUR + 228]; stage[1]  = o[CUR + 229];   // bott
        stage[2]  = o[CUR + 247]; stage[3]  = o[CUR + 248];   // dist_bott
        stage[4]  = o[CUR + 230]; stage[5]  = o[CUR + 231];   // road_end
        stage[6]  = o[CUR + 249]; stage[7]  = o[CUR + 250];   // dist_end
        stage[8]  = o[CUR + 232]; stage[9]  = o[CUR + 233];   // target
        stage[10] = o[CUR + 253];                             // gen
        stage[11] = o[CUR + 251]; stage[12] = o[CUR + 252];   // exe
        gemv_stage(ca, stage, s + OFF_CMW1 + 256 * 64, 13);
    }

    // ----- final layer: relu(relu(ca) @ cmW2 + cmb2) -----
    #pragma unroll
    for (int j = 0; j < 64; j++) stage[j] = fmaxf(ca[j], 0.f);
    initAcc(acc, s + OFF_CMB2);
    gemv_stage(acc, stage, s + OFF_CMW2, 64);

    float4* op = reinterpret_cast<float4*>(out + (long long)b * 64);
    #pragma unroll
    for (int j = 0; j < 16; j++) {
        float4 q;
        q.x = fmaxf(acc[4*j+0], 0.f);
        q.y = fmaxf(acc[4*j+1], 0.f);
        q.z = fmaxf(acc[4*j+2], 0.f);
        q.w = fmaxf(acc[4*j+3], 0.f);
        op[j] = q;
    }
}

extern "C" void kernel_launch(void* const* d_in, const int* in_sizes, int n_in,
                              void* d_out, int out_size) {
    const float* obs    = (const float*)d_in[0];
    const float* W_self = (const float*)d_in[1];
    const float* b_self = (const float*)d_in[2];
    const float* W_dyn  = (const float*)d_in[3];
    const float* b_dyn  = (const float*)d_in[4];
    const float* hWh    = (const float*)d_in[5];
    const float* ha1    = (const float*)d_in[6];
    const float* ha2    = (const float*)d_in[7];
    const float* hWo    = (const float*)d_in[8];
    const float* hao1   = (const float*)d_in[9];
    const float* hao2   = (const float*)d_in[10];
    const float* cWh    = (const float*)d_in[11];
    const float* ca1v   = (const float*)d_in[12];
    const float* ca2v   = (const float*)d_in[13];
    const float* cWo    = (const float*)d_in[14];
    const float* cao1   = (const float*)d_in[15];
    const float* cao2   = (const float*)d_in[16];
    const float* lW1    = (const float*)d_in[17];
    const float* lb1    = (const float*)d_in[18];
    const float* lW2    = (const float*)d_in[19];
    const float* lb2    = (const float*)d_in[20];
    const float* cmW1   = (const float*)d_in[21];
    const float* cmb1   = (const float*)d_in[22];
    const float* cmW2   = (const float*)d_in[23];
    const float* cmb2   = (const float*)d_in[24];

    int B = in_sizes[0] / OBS_STRIDE;
    size_t smem = (size_t)SMEM_FLOATS * sizeof(float);
    cudaFuncSetAttribute(pred_kernel, cudaFuncAttributeMaxDynamicSharedMemorySize, (int)smem);

    dim3 block(BLOCK);
    dim3 grid(GRID);
    pred_kernel<<<grid, block, smem>>>(
        obs, W_self, b_self, W_dyn, b_dyn,
        hWh, ha1, ha2, hWo, hao1, hao2,
        cWh, ca1v, ca2v, cWo, cao1, cao2,
        lW1, lb1, lW2, lb2,
        cmW1, cmb1, cmW2, cmb2,
        (float*)d_out, B);
}

// round 16
// speedup vs baseline: 1.4724x; 1.2611x over previous
#include <cuda_runtime.h>

#define DEV __device__ __forceinline__

// ---------------- shared-memory weight layout (floats) ----------------
static constexpr int OFF_WSELF = 0;                       // 15*128
static constexpr int OFF_BSELF = OFF_WSELF + 15 * 128;    // 128
static constexpr int OFF_WDYN  = OFF_BSELF + 128;         // 128*64
static constexpr int OFF_BDYN  = OFF_WDYN + 128 * 64;     // 64
static constexpr int OFF_HWH   = OFF_BDYN + 64;           // 3*3*16
static constexpr int OFF_HA1   = OFF_HWH + 144;           // 48
static constexpr int OFF_HA2   = OFF_HA1 + 48;            // 48
static constexpr int OFF_HWO   = OFF_HA2 + 48;            // 48*64
static constexpr int OFF_HWA1  = OFF_HWO + 48 * 64;       // 48  (hWo @ hao1)
static constexpr int OFF_HWA2  = OFF_HWA1 + 48;           // 48  (hWo @ hao2)
static constexpr int OFF_CWH   = OFF_HWA2 + 48;
static constexpr int OFF_CA1   = OFF_CWH + 144;
static constexpr int OFF_CA2   = OFF_CA1 + 48;
static constexpr int OFF_CWO   = OFF_CA2 + 48;
static constexpr int OFF_CWA1  = OFF_CWO + 48 * 64;
static constexpr int OFF_CWA2  = OFF_CWA1 + 48;
static constexpr int OFF_LW1   = OFF_CWA2 + 48;           // 108*64
static constexpr int OFF_LB1   = OFF_LW1 + 108 * 64;      // 64
static constexpr int OFF_LW2   = OFF_LB1 + 64;            // 64*64
static constexpr int OFF_LB2   = OFF_LW2 + 64 * 64;       // 64
static constexpr int OFF_CMW1  = OFF_LB2 + 64;            // 269*64
static constexpr int OFF_CMB1  = OFF_CMW1 + 269 * 64;     // 64
static constexpr int OFF_CMW2  = OFF_CMB1 + 64;           // 64*64
static constexpr int OFF_CMB2  = OFF_CMW2 + 64 * 64;      // 64
static constexpr int SMEM_FLOATS = OFF_CMB2 + 64;         // 49696 floats = 198784 B

static constexpr int OBS_STRIDE = 2064;   // 6 * 344
static constexpr int CUR = 5 * 344;       // 1720

static constexpr int BLOCK = 224;
static constexpr int GRID  = 148;

DEV float lrelu2(float z)  { return z > 0.f ? z : 0.01f * z; }  // leaky(leaky(.,0.1),0.1)
DEV float lrelu02(float z) { return z > 0.f ? z : 0.2f  * z; }
DEV float eluf(float z)    { return z > 0.f ? z : (__expf(z) - 1.f); }

DEV void cp4(float* dst, const float* __restrict__ src, int n4, int tid, int bd) {
    float4* d = reinterpret_cast<float4*>(dst);
    const float4* sp = reinterpret_cast<const float4*>(src);
    for (int i = tid; i < n4; i += bd) d[i] = sp[i];
}

// acc[64] += v * row[0..63] (smem, 16B aligned). Fully unrolled (static acc idx).
DEV void gv64(float (&acc)[64], float v, const float* row) {
    const float4* w = reinterpret_cast<const float4*>(row);
    #pragma unroll
    for (int j = 0; j < 16; j++) {
        float4 q = w[j];
        acc[4*j+0] = fmaf(v, q.x, acc[4*j+0]);
        acc[4*j+1] = fmaf(v, q.y, acc[4*j+1]);
        acc[4*j+2] = fmaf(v, q.z, acc[4*j+2]);
        acc[4*j+3] = fmaf(v, q.w, acc[4*j+3]);
    }
}

// Dual-k GEMV step: acc += v0*r0 + v1*r1. Per-accumulator order (v0 then v1)
// matches serial k,k+1 -> identical numerics. Both row-load batches issue ahead
// of the FMA drain, covering LDS head latency across the loop back-edge.
DEV void gv64_2(float (&acc)[64], float v0, float v1, const float* r0, const float* r1) {
    const float4* w0 = reinterpret_cast<const float4*>(r0);
    const float4* w1 = reinterpret_cast<const float4*>(r1);
    #pragma unroll
    for (int j = 0; j < 16; j++) {
        float4 q0 = w0[j];
        float4 q1 = w1[j];
        acc[4*j+0] = fmaf(v0, q0.x, acc[4*j+0]);
        acc[4*j+1] = fmaf(v0, q0.y, acc[4*j+1]);
        acc[4*j+2] = fmaf(v0, q0.z, acc[4*j+2]);
        acc[4*j+3] = fmaf(v0, q0.w, acc[4*j+3]);
        acc[4*j+0] = fmaf(v1, q1.x, acc[4*j+0]);
        acc[4*j+1] = fmaf(v1, q1.y, acc[4*j+1]);
        acc[4*j+2] = fmaf(v1, q1.z, acc[4*j+2]);
        acc[4*j+3] = fmaf(v1, q1.w, acc[4*j+3]);
    }
}

// acc[64] += stage[0..K-1] (per-thread local memory) @ sW[K x 64] (smem rows).
// THE single delta vs the 175.9us kernel: unroll 2 over k.
DEV void gemv_stage(float (&acc)[64], volatile const float* st, const float* sW, int K) {
    int k = 0;
    #pragma unroll 1
    for (; k + 1 < K; k += 2) {
        float v0 = st[k];
        float v1 = st[k + 1];
        gv64_2(acc, v0, v1, sW + k * 64, sW + k * 64 + 64);
    }
    if (k < K) gv64(acc, st[k], sW + k * 64);
}

DEV void initAcc(float (&acc)[64], const float* bias) {
    const float4* bp = reinterpret_cast<const float4*>(bias);
    #pragma unroll
    for (int j = 0; j < 16; j++) {
        float4 q = bp[j];
        acc[4*j+0] = q.x; acc[4*j+1] = q.y; acc[4*j+2] = q.z; acc[4*j+3] = q.w;
    }
}

// Star-GAT collapsed (EXACT 175.9us version: register x2e/x2o arrays).
template<int N>
DEV void gat_blend(const float* __restrict__ xin,       // nodes 1..N-1, stride 6, first 3 floats
                   float e0, float e1, float e2,        // ego node coords
                   const float* s, int WH, int A1, int A2, int WA1, int WA2,
                   float (&x2e)[48])
{
    float x2o[48];
    #pragma unroll
    for (int h = 0; h < 3; h++) {
        const float* Wh = s + WH + h * 48;   // [3][16]
        const float* a1 = s + A1 + h * 16;
        const float* a2 = s + A2 + h * 16;
        float h0[16];
        float s1 = 0.f, s20 = 0.f;
        #pragma unroll
        for (int t = 0; t < 16; t++) {
            float hv = fmaf(e0, Wh[t], fmaf(e1, Wh[16 + t], e2 * Wh[32 + t]));
            h0[t] = hv;
            s1  = fmaf(a1[t], hv, s1);
            s20 = fmaf(a2[t], hv, s20);
        }
        float w0 = __expf(lrelu02(s1 + s20));
        float den = w0;
        float ws[16];
        #pragma unroll
        for (int t = 0; t < 16; t++) ws[t] = w0 * h0[t];
        #pragma unroll 1
        for (int m = 0; m < N - 1; m++) {
            const float* xp = xin + m * 6;
            float x0 = xp[0], x1 = xp[1], x2v = xp[2];
            float hm[16]; float s2 = 0.f;
            #pragma unroll
            for (int t = 0; t < 16; t++) {
                float hv = fmaf(x0, Wh[t], fmaf(x1, Wh[16 + t], x2v * Wh[32 + t]));
                hm[t] = hv;
                s2 = fmaf(a2[t], hv, s2);
            }
            float wm = __expf(lrelu02(s1 + s2));
            den += wm;
            #pragma unroll
            for (int t = 0; t < 16; t++) ws[t] = fmaf(wm, hm[t], ws[t]);
        }
        float inv = __fdividef(1.f, den);
        #pragma unroll
        for (int t = 0; t < 16; t++) {
            x2e[h * 16 + t] = eluf(ws[t] * inv);   // ego layer-1 output (concat heads)
            x2o[h * 16 + t] = eluf(h0[t]);         // identical layer-1 output of every non-ego node
        }
    }
    float d1e = 0.f, d2e = 0.f, d2o = 0.f;
    #pragma unroll
    for (int k = 0; k < 48; k++) {
        d1e = fmaf(x2e[k], s[WA1 + k], d1e);
        d2e = fmaf(x2e[k], s[WA2 + k], d2e);
        d2o = fmaf(x2o[k], s[WA2 + k], d2o);
    }
    float we = __expf(lrelu02(d1e + d2e));
    float wo = (float)(N - 1) * __expf(lrelu02(d1e + d2o));
    float inv = __fdividef(1.f, we + wo);
    we *= inv; wo *= inv;
    #pragma unroll
    for (int k = 0; k < 48; k++) x2e[k] = fmaf(we, x2e[k], wo * x2o[k]);  // x2o dies here
}

__global__ void __launch_bounds__(BLOCK, 1) pred_kernel(
    const float* __restrict__ obs,
    const float* __restrict__ W_self, const float* __restrict__ b_self,
    const float* __restrict__ W_dyn,  const float* __restrict__ b_dyn,
    const float* __restrict__ hWh, const float* __restrict__ ha1, const float* __restrict__ ha2,
    const float* __restrict__ hWo, const float* __restrict__ hao1, const float* __restrict__ hao2,
    const float* __restrict__ cWh, const float* __restrict__ ca1v, const float* __restrict__ ca2v,
    const float* __restrict__ cWo, const float* __restrict__ cao1, const float* __restrict__ cao2,
    const float* __restrict__ lW1, const float* __restrict__ lb1,
    const float* __restrict__ lW2, const float* __restrict__ lb2,
    const float* __restrict__ cmW1, const float* __restrict__ cmb1,
    const float* __restrict__ cmW2, const float* __restrict__ cmb2,
    float* __restrict__ out, int B)
{
    extern __shared__ float s[];
    const int tid = threadIdx.x, bd = blockDim.x;

    cp4(s + OFF_WSELF, W_self, 15 * 128 / 4, tid, bd);
    cp4(s + OFF_BSELF, b_self, 128 / 4, tid, bd);
    cp4(s + OFF_WDYN,  W_dyn,  128 * 64 / 4, tid, bd);
    cp4(s + OFF_BDYN,  b_dyn,  64 / 4, tid, bd);
    cp4(s + OFF_HWH,   hWh,    144 / 4, tid, bd);
    cp4(s + OFF_HA1,   ha1,    48 / 4, tid, bd);
    cp4(s + OFF_HA2,   ha2,    48 / 4, tid, bd);
    cp4(s + OFF_HWO,   hWo,    48 * 64 / 4, tid, bd);
    cp4(s + OFF_CWH,   cWh,    144 / 4, tid, bd);
    cp4(s + OFF_CA1,   ca1v,   48 / 4, tid, bd);
    cp4(s + OFF_CA2,   ca2v,   48 / 4, tid, bd);
    cp4(s + OFF_CWO,   cWo,    48 * 64 / 4, tid, bd);
    cp4(s + OFF_LW1,   lW1,    108 * 64 / 4, tid, bd);
    cp4(s + OFF_LB1,   lb1,    64 / 4, tid, bd);
    cp4(s + OFF_LW2,   lW2,    64 * 64 / 4, tid, bd);
    cp4(s + OFF_LB2,   lb2,    64 / 4, tid, bd);
    cp4(s + OFF_CMW1,  cmW1,   269 * 64 / 4, tid, bd);
    cp4(s + OFF_CMB1,  cmb1,   64 / 4, tid, bd);
    cp4(s + OFF_CMW2,  cmW2,   64 * 64 / 4, tid, bd);
    cp4(s + OFF_CMB2,  cmb2,   64 / 4, tid, bd);

    // Precompute Wo@ao1 / Wo@ao2 for both GATs (48 values each)
    if (tid < 192) {
        int g = tid / 48;
        int r = tid - g * 48;
        const float* Wo = (g < 2) ? hWo : cWo;
        const float* ao = (g == 0) ? hao1 : (g == 1) ? hao2 : (g == 2) ? cao1 : cao2;
        int dst = (g == 0) ? OFF_HWA1 : (g == 1) ? OFF_HWA2 : (g == 2) ? OFF_CWA1 : OFF_CWA2;
        float sum = 0.f;
        #pragma unroll 1
        for (int j = 0; j < 64; j++) sum = fmaf(Wo[r * 64 + j], ao[j], sum);
        s[dst + r] = sum;
    }
    __syncthreads();

    const int b = blockIdx.x * BLOCK + tid;
    if (b >= B) return;
    const float* o = obs + (long long)b * OBS_STRIDE;

    volatile float stage[64];   // per-thread local-memory staging for GEMV multipliers
    float ca[64];               // comb-MLP hidden accumulator (persists)
    float acc[64];              // working accumulator (reused)

    initAcc(ca, s + OFF_CMB1);

    const float e0g = o[CUR + 234], e1g = o[CUR + 235], e2g = o[CUR + 236];

    // ----- HDV GAT (comb rows 64..127) -----
    {
        float xb[48];
        gat_blend<13>(o + CUR + 0, e0g, e1g, e2g, s, OFF_HWH, OFF_HA1, OFF_HA2, OFF_HWA1, OFF_HWA2, xb);
        #pragma unroll
        for (int k = 0; k < 48; k++) stage[k] = xb[k];
    }
    #pragma unroll
    for (int j = 0; j < 64; j++) acc[j] = 0.f;
    gemv_stage(acc, stage, s + OFF_HWO, 48);
    #pragma unroll
    for (int j = 0; j < 64; j++) stage[j] = eluf(acc[j]);
    gemv_stage(ca, stage, s + OFF_CMW1 + 64 * 64, 64);

    // ----- CAV GAT (comb rows 128..191) -----
    {
        float xb[48];
        gat_blend<9>(o + CUR + 72, e0g, e1g, e2g, s, OFF_CWH, OFF_CA1, OFF_CA2, OFF_CWA1, OFF_CWA2, xb);
        #pragma unroll
        for (int k = 0; k < 48; k++) stage[k] = xb[k];
    }
    #pragma unroll
    for (int j = 0; j < 64; j++) acc[j] = 0.f;
    gemv_stage(acc, stage, s + OFF_CWO, 48);
    #pragma unroll
    for (int j = 0; j < 64; j++) stage[j] = eluf(acc[j]);
    gemv_stage(ca, stage, s + OFF_CMW1 + 128 * 64, 64);

    // ----- ego feature (comb rows 0..63): leaky2(ehist@W_self+b_self)@W_dyn+b_dyn -----
    initAcc(acc, s + OFF_BDYN);
    {
        float eh[15];
        #pragma unroll
        for (int st = 0; st < 5; st++) {
            const float* p = o + (st + 1) * 344 + 234;
            eh[st * 3 + 0] = p[0];
            eh[st * 3 + 1] = p[1];
            eh[st * 3 + 2] = p[2];
        }
        #pragma unroll 1
        for (int k = 0; k < 128; k++) {
            float z = s[OFF_BSELF + k];
            #pragma unroll
            for (int i = 0; i < 15; i++) z = fmaf(eh[i], s[OFF_WSELF + i * 128 + k], z);
            gv64(acc, lrelu2(z), s + OFF_WDYN + k * 64);
        }
    }
    #pragma unroll
    for (int j = 0; j < 64; j++) stage[j] = acc[j];
    gemv_stage(ca, stage, s + OFF_CMW1 + 0 * 64, 64);

    // ----- lane MLP (comb rows 192..255) -----
    initAcc(acc, s + OFF_LB1);
    {
        const float4* lp = reinterpret_cast<const float4*>(o + CUR + 120);
        #pragma unroll 1
        for (int k4 = 0; k4 < 27; k4++) {
            float4 v = lp[k4];
            gv64(acc, v.x, s + OFF_LW1 + (4 * k4 + 0) * 64);
            gv64(acc, v.y, s + OFF_LW1 + (4 * k4 + 1) * 64);
            gv64(acc, v.z, s + OFF_LW1 + (4 * k4 + 2) * 64);
            gv64(acc, v.w, s + OFF_LW1 + (4 * k4 + 3) * 64);
        }
    }
    #pragma unroll
    for (int j = 0; j < 64; j++) stage[j] = fmaxf(acc[j], 0.f);
    initAcc(acc, s + OFF_LB2);
    gemv_stage(acc, stage, s + OFF_LW2, 64);
    #pragma unroll
    for (int j = 0; j < 64; j++) stage[j] = fmaxf(acc[j], 0.f);
    gemv_stage(ca, stage, s + OFF_CMW1 + 192 * 64, 64);

    // ----- road / gen / exe (comb rows 256..268) -----
    {
        stage[0]  = o[CUR + 228]; stage[1]  = o[CUR + 229];   // bott
        stage[2]  = o[CUR + 247]; stage[3]  = o[CUR + 248];   // dist_bott
        stage[4]  = o[CUR + 230]; stage[5]  = o[CUR + 231];   // road_end
        stage[6]  = o[CUR + 249]; stage[7]  = o[CUR + 250];   // dist_end
        stage[8]  = o[CUR + 232]; stage[9]  = o[CUR + 233];   // target
        stage[10] = o[CUR + 253];                             // gen
        stage[11] = o[CUR + 251]; stage[12] = o[CUR + 252];   // exe
        gemv_stage(ca, stage, s + OFF_CMW1 + 256 * 64, 13);
    }

    // ----- final layer: relu(relu(ca) @ cmW2 + cmb2) -----
    #pragma unroll
    for (int j = 0; j < 64; j++) stage[j] = fmaxf(ca[j], 0.f);
    initAcc(acc, s + OFF_CMB2);
    gemv_stage(acc, stage, s + OFF_CMW2, 64);

    float4* op = reinterpret_cast<float4*>(out + (long long)b * 64);
    #pragma unroll
    for (int j = 0; j < 16; j++) {
        float4 q;
        q.x = fmaxf(acc[4*j+0], 0.f);
        q.y = fmaxf(acc[4*j+1], 0.f);
        q.z = fmaxf(acc[4*j+2], 0.f);
        q.w = fmaxf(acc[4*j+3], 0.f);
        op[j] = q;
    }
}

extern "C" void kernel_launch(void* const* d_in, const int* in_sizes, int n_in,
                              void* d_out, int out_size) {
    const float* obs    = (const float*)d_in[0];
    const float* W_self = (const float*)d_in[1];
    const float* b_self = (const float*)d_in[2];
    const float* W_dyn  = (const float*)d_in[3];
    const float* b_dyn  = (const float*)d_in[4];
    const float* hWh    = (const float*)d_in[5];
    const float* ha1    = (const float*)d_in[6];
    const float* ha2    = (const float*)d_in[7];
    const float* hWo    = (const float*)d_in[8];
    const float* hao1   = (const float*)d_in[9];
    const float* hao2   = (const float*)d_in[10];
    const float* cWh    = (const float*)d_in[11];
    const float* ca1v   = (const float*)d_in[12];
    const float* ca2v   = (const float*)d_in[13];
    const float* cWo    = (const float*)d_in[14];
    const float* cao1   = (const float*)d_in[15];
    const float* cao2   = (const float*)d_in[16];
    const float* lW1    = (const float*)d_in[17];
    const float* lb1    = (const float*)d_in[18];
    const float* lW2    = (const float*)d_in[19];
    const float* lb2    = (const float*)d_in[20];
    const float* cmW1   = (const float*)d_in[21];
    const float* cmb1   = (const float*)d_in[22];
    const float* cmW2   = (const float*)d_in[23];
    const float* cmb2   = (const float*)d_in[24];

    int B = in_sizes[0] / OBS_STRIDE;
    size_t smem = (size_t)SMEM_FLOATS * sizeof(float);
    cudaFuncSetAttribute(pred_kernel, cudaFuncAttributeMaxDynamicSharedMemorySize, (int)smem);

    dim3 block(BLOCK);
    dim3 grid(GRID);
    pred_kernel<<<grid, block, smem>>>(
        obs, W_self, b_self, W_dyn, b_dyn,
        hWh, ha1, ha2, hWo, hao1, hao2,
        cWh, ca1v, ca2v, cWo, cao1, cao2,
        lW1, lb1, lW2, lb2,
        cmW1, cmb1, cmW2, cmb2,
        (float*)d_out, B);
}

// round 17
// speedup vs baseline: 1.6245x; 1.1033x over previous
#include <cuda_runtime.h>

#define DEV __device__ __forceinline__
typedef unsigned long long u64;

// ---------------- shared-memory weight layout (floats) ----------------
static constexpr int OFF_WSELF = 0;                       // 15*128
static constexpr int OFF_BSELF = OFF_WSELF + 15 * 128;    // 128
static constexpr int OFF_WDYN  = OFF_BSELF + 128;         // 128*64  (holds WFUSE = W_dyn @ CMW1_ego)
static constexpr int OFF_BDYN  = OFF_WDYN + 128 * 64;     // 64
static constexpr int OFF_HWH   = OFF_BDYN + 64;           // 3*3*16
static constexpr int OFF_HA1   = OFF_HWH + 144;           // 48
static constexpr int OFF_HA2   = OFF_HA1 + 48;            // 48
static constexpr int OFF_HWO   = OFF_HA2 + 48;            // 48*64
static constexpr int OFF_HWA1  = OFF_HWO + 48 * 64;       // 48  (hWo @ hao1)
static constexpr int OFF_HWA2  = OFF_HWA1 + 48;           // 48  (hWo @ hao2)
static constexpr int OFF_CWH   = OFF_HWA2 + 48;
static constexpr int OFF_CA1   = OFF_CWH + 144;
static constexpr int OFF_CA2   = OFF_CA1 + 48;
static constexpr int OFF_CWO   = OFF_CA2 + 48;
static constexpr int OFF_CWA1  = OFF_CWO + 48 * 64;
static constexpr int OFF_CWA2  = OFF_CWA1 + 48;
static constexpr int OFF_LW1   = OFF_CWA2 + 48;           // 108*64
static constexpr int OFF_LB1   = OFF_LW1 + 108 * 64;      // 64
static constexpr int OFF_LW2   = OFF_LB1 + 64;            // 64*64
static constexpr int OFF_LB2   = OFF_LW2 + 64 * 64;       // 64
static constexpr int OFF_CMW1  = OFF_LB2 + 64;            // 269*64 (rows 0..63 unused at runtime)
static constexpr int OFF_CMB1  = OFF_CMW1 + 269 * 64;     // 64 (holds fused bias)
static constexpr int OFF_CMW2  = OFF_CMB1 + 64;           // 64*64
static constexpr int OFF_CMB2  = OFF_CMW2 + 64 * 64;      // 64
static constexpr int SMEM_FLOATS = OFF_CMB2 + 64;         // 49696 floats = 198784 B

static constexpr int OBS_STRIDE = 2064;   // 6 * 344
static constexpr int CUR = 5 * 344;       // 1720

static constexpr int BLOCK = 224;
static constexpr int GRID  = 148;

// prep-kernel outputs (scratch via __device__ globals -- allocation-free)
__device__ float g_wfuse[128 * 64];
__device__ float g_bfuse[64];

DEV float lrelu2(float z)  { return z > 0.f ? z : 0.01f * z; }  // leaky(leaky(.,0.1),0.1)
DEV float lrelu02(float z) { return z > 0.f ? z : 0.2f  * z; }
DEV float eluf(float z)    { return z > 0.f ? z : (__expf(z) - 1.f); }

// ---- packed f32x2 helpers (FFMA2; per-lane math identical to scalar fmaf) ----
DEV u64 pk(float x)                     { u64 r; asm("mov.b64 %0, {%1, %1};" : "=l"(r) : "f"(x)); return r; }
DEV void upk(u64 v, float& x, float& y) { asm("mov.b64 {%0, %1}, %2;" : "=f"(x), "=f"(y) : "l"(v)); }
DEV void fma2(u64& d, u64 a, u64 b)     { asm("fma.rn.f32x2 %0, %1, %2, %0;" : "+l"(d) : "l"(a), "l"(b)); }

DEV void cp4(float* dst, const float* __restrict__ src, int n4, int tid, int bd) {
    float4* d = reinterpret_cast<float4*>(dst);
    const float4* sp = reinterpret_cast<const float4*>(src);
    for (int i = tid; i < n4; i += bd) d[i] = sp[i];
}

// pa[i] holds output columns (2i, 2i+1). pa += v * row[0..63].
DEV void gv_pk(u64 (&pa)[32], float v, const float* row) {
    u64 v2 = pk(v);
    const ulonglong2* w = reinterpret_cast<const ulonglong2*>(row);
    #pragma unroll
    for (int j = 0; j < 16; j++) {
        ulonglong2 q = w[j];
        fma2(pa[2 * j + 0], v2, q.x);
        fma2(pa[2 * j + 1], v2, q.y);
    }
}

// Dual-k packed step: pa += v0*r0 + v1*r1 (per-accumulator order v0 then v1 ==
// serial k,k+1). Both row-load batches issue ahead of the FFMA2 drain.
DEV void gv_pk2(u64 (&pa)[32], float v0, float v1, const float* r0, const float* r1) {
    u64 a2 = pk(v0), b2 = pk(v1);
    const ulonglong2* w0 = reinterpret_cast<const ulonglong2*>(r0);
    const ulonglong2* w1 = reinterpret_cast<const ulonglong2*>(r1);
    #pragma unroll
    for (int j = 0; j < 16; j++) {
        ulonglong2 q0 = w0[j];
        ulonglong2 q1 = w1[j];
        fma2(pa[2 * j + 0], a2, q0.x);
        fma2(pa[2 * j + 1], a2, q0.y);
        fma2(pa[2 * j + 0], b2, q1.x);
        fma2(pa[2 * j + 1], b2, q1.y);
    }
}

// pa += stage[0..K-1] (local mem) @ sW[K x 64] (smem rows), unroll 2 over k.
DEV void gemv_pk(u64 (&pa)[32], volatile const float* st, const float* sW, int K) {
    int k = 0;
    #pragma unroll 1
    for (; k + 1 < K; k += 2) {
        float v0 = st[k];
        float v1 = st[k + 1];
        gv_pk2(pa, v0, v1, sW + k * 64, sW + k * 64 + 64);
    }
    if (k < K) gv_pk(pa, st[k], sW + k * 64);
}

DEV void initPk(u64 (&pa)[32], const float* bias) {
    const ulonglong2* bp = reinterpret_cast<const ulonglong2*>(bias);
    #pragma unroll
    for (int j = 0; j < 16; j++) {
        ulonglong2 q = bp[j];
        pa[2 * j + 0] = q.x;
        pa[2 * j + 1] = q.y;
    }
}

// Star-GAT collapsed (register x2e/x2o, as the 172.5us kernel).
template<int N>
DEV void gat_blend(const float* __restrict__ xin,       // nodes 1..N-1, stride 6, first 3 floats
                   float e0, float e1, float e2,        // ego node coords
                   const float* s, int WH, int A1, int A2, int WA1, int WA2,
                   float (&x2e)[48])
{
    float x2o[48];
    #pragma unroll
    for (int h = 0; h < 3; h++) {
        const float* Wh = s + WH + h * 48;   // [3][16]
        const float* a1 = s + A1 + h * 16;
        const float* a2 = s + A2 + h * 16;
        float h0[16];
        float s1 = 0.f, s20 = 0.f;
        #pragma unroll
        for (int t = 0; t < 16; t++) {
            float hv = fmaf(e0, Wh[t], fmaf(e1, Wh[16 + t], e2 * Wh[32 + t]));
            h0[t] = hv;
            s1  = fmaf(a1[t], hv, s1);
            s20 = fmaf(a2[t], hv, s20);
        }
        float w0 = __expf(lrelu02(s1 + s20));
        float den = w0;
        float ws[16];
        #pragma unroll
        for (int t = 0; t < 16; t++) ws[t] = w0 * h0[t];
        #pragma unroll 1
        for (int m = 0; m < N - 1; m++) {
            const float* xp = xin + m * 6;
            float x0 = xp[0], x1 = xp[1], x2v = xp[2];
            float hm[16]; float s2 = 0.f;
            #pragma unroll
            for (int t = 0; t < 16; t++) {
                float hv = fmaf(x0, Wh[t], fmaf(x1, Wh[16 + t], x2v * Wh[32 + t]));
                hm[t] = hv;
                s2 = fmaf(a2[t], hv, s2);
            }
            float wm = __expf(lrelu02(s1 + s2));
            den += wm;
            #pragma unroll
            for (int t = 0; t < 16; t++) ws[t] = fmaf(wm, hm[t], ws[t]);
        }
        float inv = __fdividef(1.f, den);
        #pragma unroll
        for (int t = 0; t < 16; t++) {
            x2e[h * 16 + t] = eluf(ws[t] * inv);   // ego layer-1 output (concat heads)
            x2o[h * 16 + t] = eluf(h0[t]);         // identical layer-1 output of non-ego nodes
        }
    }
    float d1e = 0.f, d2e = 0.f, d2o = 0.f;
    #pragma unroll
    for (int k = 0; k < 48; k++) {
        d1e = fmaf(x2e[k], s[WA1 + k], d1e);
        d2e = fmaf(x2e[k], s[WA2 + k], d2e);
        d2o = fmaf(x2o[k], s[WA2 + k], d2o);
    }
    float we = __expf(lrelu02(d1e + d2e));
    float wo = (float)(N - 1) * __expf(lrelu02(d1e + d2o));
    float inv = __fdividef(1.f, we + wo);
    we *= inv; wo *= inv;
    #pragma unroll
    for (int k = 0; k < 48; k++) x2e[k] = fmaf(we, x2e[k], wo * x2o[k]);  // x2o dies here
}

// ---- prep kernel: WFUSE = W_dyn @ CMW1[0:64], bfuse = cmb1 + b_dyn @ CMW1[0:64] ----
__global__ void prep_kernel(const float* __restrict__ W_dyn, const float* __restrict__ cmW1,
                            const float* __restrict__ b_dyn, const float* __restrict__ cmb1) {
    int idx = blockIdx.x * blockDim.x + threadIdx.x;
    if (idx < 128 * 64) {
        int k = idx >> 6, j = idx & 63;
        float sum = 0.f;
        #pragma unroll 1
        for (int m = 0; m < 64; m++)
            sum = fmaf(W_dyn[k * 64 + m], cmW1[m * 64 + j], sum);
        g_wfuse[idx] = sum;
    }
    if (idx < 64) {
        float bf = cmb1[idx];
        #pragma unroll 1
        for (int k = 0; k < 64; k++)
            bf = fmaf(b_dyn[k], cmW1[k * 64 + idx], bf);
        g_bfuse[idx] = bf;
    }
}

__global__ void __launch_bounds__(BLOCK, 1) pred_kernel(
    const float* __restrict__ obs,
    const float* __restrict__ W_self, const float* __restrict__ b_self,
    const float* __restrict__ W_dyn,  const float* __restrict__ b_dyn,
    const float* __restrict__ hWh, const float* __restrict__ ha1, const float* __restrict__ ha2,
    const float* __restrict__ hWo, const float* __restrict__ hao1, const float* __restrict__ hao2,
    const float* __restrict__ cWh, const float* __restrict__ ca1v, const float* __restrict__ ca2v,
    const float* __restrict__ cWo, const float* __restrict__ cao1, const float* __restrict__ cao2,
    const float* __restrict__ lW1, const float* __restrict__ lb1,
    const float* __restrict__ lW2, const float* __restrict__ lb2,
    const float* __restrict__ cmW1, const float* __restrict__ cmb1,
    const float* __restrict__ cmW2, const float* __restrict__ cmb2,
    float* __restrict__ out, int B)
{
    extern __shared__ float s[];
    const int tid = threadIdx.x, bd = blockDim.x;

    cp4(s + OFF_WSELF, W_self, 15 * 128 / 4, tid, bd);
    cp4(s + OFF_BSELF, b_self, 128 / 4, tid, bd);
    cp4(s + OFF_WDYN,  g_wfuse, 128 * 64 / 4, tid, bd);   // fused ego weight
    cp4(s + OFF_BDYN,  b_dyn,  64 / 4, tid, bd);
    cp4(s + OFF_HWH,   hWh,    144 / 4, tid, bd);
    cp4(s + OFF_HA1,   ha1,    48 / 4, tid, bd);
    cp4(s + OFF_HA2,   ha2,    48 / 4, tid, bd);
    cp4(s + OFF_HWO,   hWo,    48 * 64 / 4, tid, bd);
    cp4(s + OFF_CWH,   cWh,    144 / 4, tid, bd);
    cp4(s + OFF_CA1,   ca1v,   48 / 4, tid, bd);
    cp4(s + OFF_CA2,   ca2v,   48 / 4, tid, bd);
    cp4(s + OFF_CWO,   cWo,    48 * 64 / 4, tid, bd);
    cp4(s + OFF_LW1,   lW1,    108 * 64 / 4, tid, bd);
    cp4(s + OFF_LB1,   lb1,    64 / 4, tid, bd);
    cp4(s + OFF_LW2,   lW2,    64 * 64 / 4, tid, bd);
    cp4(s + OFF_LB2,   lb2,    64 / 4, tid, bd);
    cp4(s + OFF_CMW1,  cmW1,   269 * 64 / 4, tid, bd);
    cp4(s + OFF_CMB1,  g_bfuse, 64 / 4, tid, bd);         // fused bias
    cp4(s + OFF_CMW2,  cmW2,   64 * 64 / 4, tid, bd);
    cp4(s + OFF_CMB2,  cmb2,   64 / 4, tid, bd);

    // Precompute Wo@ao1 / Wo@ao2 for both GATs (48 values each)
    if (tid < 192) {
        int g = tid / 48;
        int r = tid - g * 48;
        const float* Wo = (g < 2) ? hWo : cWo;
        const float* ao = (g == 0) ? hao1 : (g == 1) ? hao2 : (g == 2) ? cao1 : cao2;
        int dst = (g == 0) ? OFF_HWA1 : (g == 1) ? OFF_HWA2 : (g == 2) ? OFF_CWA1 : OFF_CWA2;
        float sum = 0.f;
        #pragma unroll 1
        for (int j = 0; j < 64; j++) sum = fmaf(Wo[r * 64 + j], ao[j], sum);
        s[dst + r] = sum;
    }
    __syncthreads();

    const int b = blockIdx.x * BLOCK + tid;
    if (b >= B) return;
    const float* o = obs + (long long)b * OBS_STRIDE;

    volatile float stage[64];   // per-thread local staging for GEMV multipliers
    u64 ca[32];                 // comb hidden accumulator, packed pairs (cols 2i,2i+1)
    u64 pa[32];                 // working packed accumulator

    initPk(ca, s + OFF_CMB1);   // fused bias

    const float e0g = o[CUR + 234], e1g = o[CUR + 235], e2g = o[CUR + 236];

    // ----- HDV GAT (comb rows 64..127) -----
    {
        float xb[48];
        gat_blend<13>(o + CUR + 0, e0g, e1g, e2g, s, OFF_HWH, OFF_HA1, OFF_HA2, OFF_HWA1, OFF_HWA2, xb);
        #pragma unroll
        for (int k = 0; k < 48; k++) stage[k] = xb[k];
    }
    #pragma unroll
    for (int j = 0; j < 32; j++) pa[j] = 0ull;
    gemv_pk(pa, stage, s + OFF_HWO, 48);
    #pragma unroll
    for (int j = 0; j < 32; j++) {
        float v0, v1; upk(pa[j], v0, v1);
        stage[2 * j + 0] = eluf(v0);
        stage[2 * j + 1] = eluf(v1);
    }
    gemv_pk(ca, stage, s + OFF_CMW1 + 64 * 64, 64);

    // ----- CAV GAT (comb rows 128..191) -----
    {
        float xb[48];
        gat_blend<9>(o + CUR + 72, e0g, e1g, e2g, s, OFF_CWH, OFF_CA1, OFF_CA2, OFF_CWA1, OFF_CWA2, xb);
        #pragma unroll
        for (int k = 0; k < 48; k++) stage[k] = xb[k];
    }
    #pragma unroll
    for (int j = 0; j < 32; j++) pa[j] = 0ull;
    gemv_pk(pa, stage, s + OFF_CWO, 48);
    #pragma unroll
    for (int j = 0; j < 32; j++) {
        float v0, v1; upk(pa[j], v0, v1);
        stage[2 * j + 0] = eluf(v0);
        stage[2 * j + 1] = eluf(v1);
    }
    gemv_pk(ca, stage, s + OFF_CMW1 + 128 * 64, 64);

    // ----- ego feature fused into comb rows 0..63: ca += lrelu2(eh@WSELF+b)@WFUSE -----
    {
        float eh[15];
        #pragma unroll
        for (int st5 = 0; st5 < 5; st5++) {
            const float* p = o + (st5 + 1) * 344 + 234;
            eh[st5 * 3 + 0] = p[0];
            eh[st5 * 3 + 1] = p[1];
            eh[st5 * 3 + 2] = p[2];
        }
        #pragma unroll 1
        for (int kg = 0; kg < 32; kg++) {   // 4 hidden columns per iter (float4 rows)
            float4 zb = reinterpret_cast<const float4*>(s + OFF_BSELF)[kg];
            float z0 = zb.x, z1 = zb.y, z2 = zb.z, z3 = zb.w;
            #pragma unroll
            for (int i = 0; i < 15; i++) {
                float4 w = reinterpret_cast<const float4*>(s + OFF_WSELF + i * 128)[kg];
                z0 = fmaf(eh[i], w.x, z0);
                z1 = fmaf(eh[i], w.y, z1);
                z2 = fmaf(eh[i], w.z, z2);
                z3 = fmaf(eh[i], w.w, z3);
            }
            gv_pk2(ca, lrelu2(z0), lrelu2(z1),
                   s + OFF_WDYN + (4 * kg + 0) * 64, s + OFF_WDYN + (4 * kg + 1) * 64);
            gv_pk2(ca, lrelu2(z2), lrelu2(z3),
                   s + OFF_WDYN + (4 * kg + 2) * 64, s + OFF_WDYN + (4 * kg + 3) * 64);
        }
    }

    // ----- lane MLP (comb rows 192..255) -----
    initPk(pa, s + OFF_LB1);
    {
        const float4* lp = reinterpret_cast<const float4*>(o + CUR + 120);
        #pragma unroll 1
        for (int k4 = 0; k4 < 27; k4++) {
            float4 v = lp[k4];
            gv_pk2(pa, v.x, v.y, s + OFF_LW1 + (4 * k4 + 0) * 64, s + OFF_LW1 + (4 * k4 + 1) * 64);
            gv_pk2(pa, v.z, v.w, s + OFF_LW1 + (4 * k4 + 2) * 64, s + OFF_LW1 + (4 * k4 + 3) * 64);
        }
    }
    #pragma unroll
    for (int j = 0; j < 32; j++) {
        float v0, v1; upk(pa[j], v0, v1);
        stage[2 * j + 0] = fmaxf(v0, 0.f);
        stage[2 * j + 1] = fmaxf(v1, 0.f);
    }
    initPk(pa, s + OFF_LB2);
    gemv_pk(pa, stage, s + OFF_LW2, 64);
    #pragma unroll
    for (int j = 0; j < 32; j++) {
        float v0, v1; upk(pa[j], v0, v1);
        stage[2 * j + 0] = fmaxf(v0, 0.f);
        stage[2 * j + 1] = fmaxf(v1, 0.f);
    }
    gemv_pk(ca, stage, s + OFF_CMW1 + 192 * 64, 64);

    // ----- road / gen / exe (comb rows 256..268) -----
    {
        stage[0]  = o[CUR + 228]; stage[1]  = o[CUR + 229];   // bott
        stage[2]  = o[CUR + 247]; stage[3]  = o[CUR + 248];   // dist_bott
        stage[4]  = o[CUR + 230]; stage[5]  = o[CUR + 231];   // road_end
        stage[6]  = o[CUR + 249]; stage[7]  = o[CUR + 250];   // dist_end
        stage[8]  = o[CUR + 232]; stage[9]  = o[CUR + 233];   // target
        stage[10] = o[CUR + 253];                             // gen
        stage[11] = o[CUR + 251]; stage[12] = o[CUR + 252];   // exe
        gemv_pk(ca, stage, s + OFF_CMW1 + 256 * 64, 13);
    }

    // ----- final layer: relu(relu(ca) @ cmW2 + cmb2) -----
    #pragma unroll
    for (int j = 0; j < 32; j++) {
        float v0, v1; upk(ca[j], v0, v1);
        stage[2 * j + 0] = fmaxf(v0, 0.f);
        stage[2 * j + 1] = fmaxf(v1, 0.f);
    }
    initPk(pa, s + OFF_CMB2);
    gemv_pk(pa, stage, s + OFF_CMW2, 64);

    // write all 64 outputs (pa[2j], pa[2j+1] -> float4 j; j = 0..15)
    float4* op = reinterpret_cast<float4*>(out + (long long)b * 64);
    #pragma unroll
    for (int j = 0; j < 16; j++) {
        float a0, a1c, a2c, a3;
        upk(pa[2 * j + 0], a0, a1c);
        upk(pa[2 * j + 1], a2c, a3);
        float4 q;
        q.x = fmaxf(a0, 0.f);
        q.y = fmaxf(a1c, 0.f);
        q.z = fmaxf(a2c, 0.f);
        q.w = fmaxf(a3, 0.f);
        op[j] = q;
    }
}

extern "C" void kernel_launch(void* const* d_in, const int* in_sizes, int n_in,
                              void* d_out, int out_size) {
    const float* obs    = (const float*)d_in[0];
    const float* W_self = (const float*)d_in[1];
    const float* b_self = (const float*)d_in[2];
    const float* W_dyn  = (const float*)d_in[3];
    const float* b_dyn  = (const float*)d_in[4];
    const float* hWh    = (const float*)d_in[5];
    const float* ha1    = (const float*)d_in[6];
    const float* ha2    = (const float*)d_in[7];
    const float* hWo    = (const float*)d_in[8];
    const float* hao1   = (const float*)d_in[9];
    const float* hao2   = (const float*)d_in[10];
    const float* cWh    = (const float*)d_in[11];
    const float* ca1v   = (const float*)d_in[12];
    const float* ca2v   = (const float*)d_in[13];
    const float* cWo    = (const float*)d_in[14];
    const float* cao1   = (const float*)d_in[15];
    const float* cao2   = (const float*)d_in[16];
    const float* lW1    = (const float*)d_in[17];
    const float* lb1    = (const float*)d_in[18];
    const float* lW2    = (const float*)d_in[19];
    const float* lb2    = (const float*)d_in[20];
    const float* cmW1   = (const float*)d_in[21];
    const float* cmb1   = (const float*)d_in[22];
    const float* cmW2   = (const float*)d_in[23];
    const float* cmb2   = (const float*)d_in[24];

    int B = in_sizes[0] / OBS_STRIDE;
    size_t smem = (size_t)SMEM_FLOATS * sizeof(float);
    cudaFuncSetAttribute(pred_kernel, cudaFuncAttributeMaxDynamicSharedMemorySize, (int)smem);

    // prep: fused ego weight/bias into __device__ globals (same stream -> ordered)
    prep_kernel<<<32, 256>>>(W_dyn, cmW1, b_dyn, cmb1);

    dim3 block(BLOCK);
    dim3 grid(GRID);
    pred_kernel<<<grid, block, smem>>>(
        obs, W_self, b_self, W_dyn, b_dyn,
        hWh, ha1, ha2, hWo, hao1, hao2,
        cWh, ca1v, ca2v, cWo, cao1, cao2,
        lW1, lb1, lW2, lb2,
        cmW1, cmb1, cmW2, cmb2,
        (float*)d_out, B);
}